// round 4
// baseline (speedup 1.0000x reference)
#include <cuda_runtime.h>
#include <math.h>

#define B_TOK 8192
#define D_DIM 1024
#define DFF   1024
#define E_NUM 32
#define NFLAT (B_TOK*2)

// ---------------- scratch (static device globals; no allocation) ----------------
__device__ int   g_top2[NFLAT];
__device__ int   g_offsets[E_NUM+1];
__device__ int   g_disp[NFLAT];
__device__ float g_H[(size_t)(NFLAT+64)*DFF];   // padded 64 rows so gemm2 A-tile loads never go OOB
__device__ float g_Y[(size_t)NFLAT*D_DIM];

// ---------------- gating: logits = X @ Wg + bg, then top-2 ----------------
// block = 128 tokens, 256 threads; tiled smem GEMM (BM=128, BN=32, BK=32)
__global__ void gate_kernel(const float* __restrict__ X,
                            const float* __restrict__ Wg,
                            const float* __restrict__ bg) {
    __shared__ float Xs[32][132];   // [k][token], pad 132 (16B-aligned rows)
    __shared__ float Wgs[32][36];   // [k][expert]
    __shared__ float lg[128][33];   // logits [token][expert]
    __shared__ float bgs[32];

    int tid = threadIdx.x;
    int t0  = blockIdx.x * 128;
    if (tid < 32) bgs[tid] = bg[tid];

    int tr = tid & 31;   // token group: tokens tr*4 .. tr*4+3
    int te = tid >> 5;   // expert group: experts te*4 .. te*4+3
    float acc[4][4];
#pragma unroll
    for (int i = 0; i < 4; i++)
#pragma unroll
        for (int j = 0; j < 4; j++) acc[i][j] = 0.f;

    for (int k0 = 0; k0 < D_DIM; k0 += 32) {
#pragma unroll
        for (int i = 0; i < 16; i++) {
            int lin = tid + i * 256;
            int r = lin >> 5, c = lin & 31;
            Xs[c][r] = X[(size_t)(t0 + r) * D_DIM + k0 + c];
        }
#pragma unroll
        for (int i = 0; i < 4; i++) {
            int lin = tid + i * 256;
            int r = lin >> 5, c = lin & 31;
            Wgs[r][c] = Wg[(size_t)(k0 + r) * E_NUM + c];
        }
        __syncthreads();
#pragma unroll
        for (int kk = 0; kk < 32; kk++) {
            float4 a4 = *(const float4*)&Xs[kk][tr * 4];
            float4 b4 = *(const float4*)&Wgs[kk][te * 4];
            float av[4] = {a4.x, a4.y, a4.z, a4.w};
            float bv[4] = {b4.x, b4.y, b4.z, b4.w};
#pragma unroll
            for (int i = 0; i < 4; i++)
#pragma unroll
                for (int j = 0; j < 4; j++) acc[i][j] += av[i] * bv[j];
        }
        __syncthreads();
    }
#pragma unroll
    for (int i = 0; i < 4; i++)
#pragma unroll
        for (int j = 0; j < 4; j++)
            lg[tr * 4 + i][te * 4 + j] = acc[i][j] + bgs[te * 4 + j];
    __syncthreads();

    // top-2 (jax.lax.top_k semantics: descending, first-occurrence on ties)
    if (tid < 128) {
        int t = t0 + tid;
        float v1 = -INFINITY; int i1 = 0;
        for (int e = 0; e < 32; e++) { float v = lg[tid][e]; if (v > v1) { v1 = v; i1 = e; } }
        float v2 = -INFINITY; int i2 = 0;
        for (int e = 0; e < 32; e++) {
            if (e == i1) continue;
            float v = lg[tid][e]; if (v > v2) { v2 = v; i2 = e; }
        }
        g_top2[t * 2]     = i1;
        g_top2[t * 2 + 1] = i2;
    }
}

// ---------------- histogram + exclusive offsets (single block) ----------------
__global__ void hist_kernel() {
    __shared__ int cnt[E_NUM];
    int tid = threadIdx.x;
    if (tid < E_NUM) cnt[tid] = 0;
    __syncthreads();
    for (int f = tid; f < NFLAT; f += 256) atomicAdd(&cnt[g_top2[f]], 1);
    __syncthreads();
    if (tid == 0) {
        int run = 0;
        for (int e = 0; e < E_NUM; e++) { g_offsets[e] = run; run += cnt[e]; }
        g_offsets[E_NUM] = run;
    }
}

// ---------------- stable compaction: g_disp[sorted_pos] = flat_idx ----------------
// one block per expert; block-wide inclusive scan preserves flat-index order
__global__ void compact_kernel() {
    int e = blockIdx.x;
    __shared__ int sc[256];
    __shared__ int base_s;
    int tid = threadIdx.x;
    if (tid == 0) base_s = g_offsets[e];
    __syncthreads();
    for (int s = 0; s < NFLAT; s += 256) {
        int f = s + tid;
        int flag = (g_top2[f] == e) ? 1 : 0;
        sc[tid] = flag;
        __syncthreads();
        for (int o = 1; o < 256; o <<= 1) {
            int v = (tid >= o) ? sc[tid - o] : 0;
            __syncthreads();
            sc[tid] += v;
            __syncthreads();
        }
        if (flag) g_disp[base_s + sc[tid] - 1] = f;
        __syncthreads();
        if (tid == 0) base_s += sc[255];
        __syncthreads();
    }
}

// ---------------- GEMM1: H = gelu(gather(X) @ W1[e] + b1[e]) ----------------
// 64x64 tile, BK=16, 128 threads, 4x8 per-thread micro-tile
__global__ void __launch_bounds__(128) gemm1_kernel(const float* __restrict__ X,
                                                    const float* __restrict__ W1,
                                                    const float* __restrict__ B1) {
    int e   = blockIdx.z;
    int off = g_offsets[e];
    int cnt = g_offsets[e + 1] - off;
    int row0 = blockIdx.y * 64;
    if (row0 >= cnt) return;
    int n0 = blockIdx.x * 64;

    __shared__ float As[16][68];
    __shared__ float Bs[16][64];
    __shared__ int   toks[64];

    int tid = threadIdx.x;
    if (tid < 64) {
        int r = row0 + tid;
        toks[tid] = (r < cnt) ? (g_disp[off + r] >> 1) : 0;
    }
    __syncthreads();

    const float* Wp = W1 + (size_t)e * D_DIM * DFF + n0;
    float acc[4][8];
#pragma unroll
    for (int i = 0; i < 4; i++)
#pragma unroll
        for (int j = 0; j < 8; j++) acc[i][j] = 0.f;

    int row_t = tid & 15, col_t = tid >> 4;
    for (int k0 = 0; k0 < D_DIM; k0 += 16) {
#pragma unroll
        for (int i = 0; i < 8; i++) {
            int lin = tid + i * 128;
            int r = lin >> 4, c = lin & 15;
            As[c][r] = X[(size_t)toks[r] * D_DIM + k0 + c];
        }
#pragma unroll
        for (int i = 0; i < 8; i++) {
            int lin = tid + i * 128;
            int r = lin >> 6, c = lin & 63;
            Bs[r][c] = Wp[(size_t)(k0 + r) * DFF + c];
        }
        __syncthreads();
#pragma unroll
        for (int kk = 0; kk < 16; kk++) {
            float4 a4  = *(const float4*)&As[kk][row_t * 4];
            float4 b0  = *(const float4*)&Bs[kk][col_t * 8];
            float4 b1v = *(const float4*)&Bs[kk][col_t * 8 + 4];
            float av[4] = {a4.x, a4.y, a4.z, a4.w};
            float bv[8] = {b0.x, b0.y, b0.z, b0.w, b1v.x, b1v.y, b1v.z, b1v.w};
#pragma unroll
            for (int i = 0; i < 4; i++)
#pragma unroll
                for (int j = 0; j < 8; j++) acc[i][j] += av[i] * bv[j];
        }
        __syncthreads();
    }
#pragma unroll
    for (int i = 0; i < 4; i++) {
        int r = row_t * 4 + i;
        if (row0 + r < cnt) {
            size_t srow = (size_t)(off + row0 + r);
#pragma unroll
            for (int j = 0; j < 8; j++) {
                int n = n0 + col_t * 8 + j;
                float v = acc[i][j] + B1[e * DFF + n];
                v = 0.5f * v * (1.0f + erff(v * 0.70710678118654752440f));  // exact gelu
                g_H[srow * DFF + n] = v;
            }
        }
    }
}

// ---------------- GEMM2: Y = H @ W2[e] + b2[e] (stored in sorted order) ----------------
__global__ void __launch_bounds__(128) gemm2_kernel(const float* __restrict__ W2,
                                                    const float* __restrict__ B2) {
    int e   = blockIdx.z;
    int off = g_offsets[e];
    int cnt = g_offsets[e + 1] - off;
    int row0 = blockIdx.y * 64;
    if (row0 >= cnt) return;
    int n0 = blockIdx.x * 64;

    __shared__ float As[16][68];
    __shared__ float Bs[16][64];

    int tid = threadIdx.x;
    const float* Wp = W2 + (size_t)e * DFF * D_DIM + n0;
    const float* Ap = g_H + (size_t)(off + row0) * DFF;  // padded: OOB rows read garbage, stores guarded

    float acc[4][8];
#pragma unroll
    for (int i = 0; i < 4; i++)
#pragma unroll
        for (int j = 0; j < 8; j++) acc[i][j] = 0.f;

    int row_t = tid & 15, col_t = tid >> 4;
    for (int k0 = 0; k0 < DFF; k0 += 16) {
#pragma unroll
        for (int i = 0; i < 8; i++) {
            int lin = tid + i * 128;
            int r = lin >> 4, c = lin & 15;
            As[c][r] = Ap[(size_t)r * DFF + k0 + c];
        }
#pragma unroll
        for (int i = 0; i < 8; i++) {
            int lin = tid + i * 128;
            int r = lin >> 6, c = lin & 63;
            Bs[r][c] = Wp[(size_t)(k0 + r) * D_DIM + c];
        }
        __syncthreads();
#pragma unroll
        for (int kk = 0; kk < 16; kk++) {
            float4 a4  = *(const float4*)&As[kk][row_t * 4];
            float4 b0  = *(const float4*)&Bs[kk][col_t * 8];
            float4 b1v = *(const float4*)&Bs[kk][col_t * 8 + 4];
            float av[4] = {a4.x, a4.y, a4.z, a4.w};
            float bv[8] = {b0.x, b0.y, b0.z, b0.w, b1v.x, b1v.y, b1v.z, b1v.w};
#pragma unroll
            for (int i = 0; i < 4; i++)
#pragma unroll
                for (int j = 0; j < 8; j++) acc[i][j] += av[i] * bv[j];
        }
        __syncthreads();
    }
#pragma unroll
    for (int i = 0; i < 4; i++) {
        int r = row_t * 4 + i;
        if (row0 + r < cnt) {
            size_t srow = (size_t)(off + row0 + r);
#pragma unroll
            for (int j = 0; j < 8; j++) {
                int n = n0 + col_t * 8 + j;
                g_Y[srow * D_DIM + n] = acc[i][j] + B2[e * D_DIM + n];
            }
        }
    }
}

// ---------------- pair reduce: out[j] = Y[2j] + Y[2j+1] (matches reference reshape-sum) ----------------
__global__ void reduce_kernel(float* __restrict__ out) {
    int i = blockIdx.x * 256 + threadIdx.x;  // over float4 units
    const int n4pr = D_DIM / 4;              // 256
    int total = B_TOK * n4pr;
    if (i < total) {
        const float4* Y4 = (const float4*)g_Y;
        float4* O4 = (float4*)out;
        int j  = i / n4pr;
        int n4 = i - j * n4pr;
        float4 a = Y4[(size_t)(2 * j) * n4pr + n4];
        float4 b = Y4[(size_t)(2 * j + 1) * n4pr + n4];
        O4[i] = make_float4(a.x + b.x, a.y + b.y, a.z + b.z, a.w + b.w);
    }
}

// ---------------- gate_top_k_idx output (as float, appended after moe_outp) ----------------
__global__ void idx_kernel(float* __restrict__ out) {
    int i = blockIdx.x * 256 + threadIdx.x;
    if (i < NFLAT) out[(size_t)B_TOK * D_DIM + i] = (float)g_top2[i];
}

// ---------------- launch ----------------
extern "C" void kernel_launch(void* const* d_in, const int* in_sizes, int n_in,
                              void* d_out, int out_size) {
    const float* X  = (const float*)d_in[0];  // moe_inp (B, D)
    const float* Wg = (const float*)d_in[1];  // (D, E)
    const float* bg = (const float*)d_in[2];  // (E,)
    const float* w1 = (const float*)d_in[3];  // (E, D, DFF)
    const float* b1 = (const float*)d_in[4];  // (E, DFF)
    const float* w2 = (const float*)d_in[5];  // (E, DFF, D)
    const float* b2 = (const float*)d_in[6];  // (E, D)
    float* out = (float*)d_out;

    gate_kernel<<<B_TOK / 128, 256>>>(X, Wg, bg);
    hist_kernel<<<1, 256>>>();
    compact_kernel<<<E_NUM, 256>>>();

    dim3 ggrid(D_DIM / 64, NFLAT / 64, E_NUM);  // (ntiles, max row tiles, experts); early-exit on empty tiles
    gemm1_kernel<<<ggrid, 128>>>(X, w1, b1);
    gemm2_kernel<<<ggrid, 128>>>(w2, b2);

    reduce_kernel<<<(B_TOK * (D_DIM / 4) + 255) / 256, 256>>>(out);
    if (out_size >= B_TOK * D_DIM + NFLAT)
        idx_kernel<<<(NFLAT + 255) / 256, 256>>>(out);
}

// round 6
// speedup vs baseline: 2.6690x; 2.6690x over previous
#include <cuda_runtime.h>
#include <cuda_bf16.h>
#include <math.h>
#include <stdint.h>

#define B_TOK 8192
#define D_DIM 1024
#define DFF   1024
#define E_NUM 32
#define NFLAT (B_TOK*2)
#define NPAD  (NFLAT+128)

// ---------------- scratch (static device globals; no allocation) ----------------
__device__ int   g_top2[NFLAT];
__device__ int   g_offsets[E_NUM+1];
__device__ int   g_disp[NFLAT];
__device__ __align__(16) __nv_bfloat16 g_Xh[(size_t)NPAD*D_DIM];
__device__ __align__(16) __nv_bfloat16 g_Xl[(size_t)NPAD*D_DIM];
__device__ __align__(16) __nv_bfloat16 g_Hh[(size_t)NPAD*DFF];
__device__ __align__(16) __nv_bfloat16 g_Hl[(size_t)NPAD*DFF];
__device__ __align__(16) __nv_bfloat16 g_wh[2][(size_t)E_NUM*D_DIM*DFF];  // transposed [e][n][k], hi
__device__ __align__(16) __nv_bfloat16 g_wl[2][(size_t)E_NUM*D_DIM*DFF];  // transposed [e][n][k], lo
__device__ __align__(16) float g_Y[(size_t)NFLAT*D_DIM];

// ---------------- helpers ----------------
__device__ __forceinline__ uint32_t smem_u32(const void* p) {
    uint32_t a;
    asm("{ .reg .u64 t; cvta.to.shared.u64 t, %1; cvt.u32.u64 %0, t; }" : "=r"(a) : "l"(p));
    return a;
}
__device__ __forceinline__ uint32_t lds32(uint32_t a) {
    uint32_t v;
    asm volatile("ld.shared.b32 %0, [%1];" : "=r"(v) : "r"(a));
    return v;
}
#define CP16(dst, src) \
    asm volatile("cp.async.cg.shared.global [%0], [%1], 16;" :: "r"(dst), "l"(src) : "memory")
#define CP_COMMIT() asm volatile("cp.async.commit_group;" ::: "memory")
#define CP_WAIT(n)  asm volatile("cp.async.wait_group %0;" :: "n"(n) : "memory")

__device__ __forceinline__ void mma16816(float* c, const uint32_t* a, const uint32_t* b) {
    asm volatile(
        "mma.sync.aligned.m16n8k16.row.col.f32.bf16.bf16.f32 "
        "{%0,%1,%2,%3}, {%4,%5,%6,%7}, {%8,%9}, {%0,%1,%2,%3};"
        : "+f"(c[0]), "+f"(c[1]), "+f"(c[2]), "+f"(c[3])
        : "r"(a[0]), "r"(a[1]), "r"(a[2]), "r"(a[3]), "r"(b[0]), "r"(b[1]));
}

// ---------------- gating: logits = X @ Wg + bg, then top-2 (proven) ----------------
__global__ void gate_kernel(const float* __restrict__ X,
                            const float* __restrict__ Wg,
                            const float* __restrict__ bg) {
    __shared__ float Xs[32][132];
    __shared__ float Wgs[32][36];
    __shared__ float lg[128][33];
    __shared__ float bgs[32];

    int tid = threadIdx.x;
    int t0  = blockIdx.x * 128;
    if (tid < 32) bgs[tid] = bg[tid];

    int tr = tid & 31;
    int te = tid >> 5;
    float acc[4][4];
#pragma unroll
    for (int i = 0; i < 4; i++)
#pragma unroll
        for (int j = 0; j < 4; j++) acc[i][j] = 0.f;

    for (int k0 = 0; k0 < D_DIM; k0 += 32) {
#pragma unroll
        for (int i = 0; i < 16; i++) {
            int lin = tid + i * 256;
            int r = lin >> 5, c = lin & 31;
            Xs[c][r] = X[(size_t)(t0 + r) * D_DIM + k0 + c];
        }
#pragma unroll
        for (int i = 0; i < 4; i++) {
            int lin = tid + i * 256;
            int r = lin >> 5, c = lin & 31;
            Wgs[r][c] = Wg[(size_t)(k0 + r) * E_NUM + c];
        }
        __syncthreads();
#pragma unroll
        for (int kk = 0; kk < 32; kk++) {
            float4 a4 = *(const float4*)&Xs[kk][tr * 4];
            float4 b4 = *(const float4*)&Wgs[kk][te * 4];
            float av[4] = {a4.x, a4.y, a4.z, a4.w};
            float bv[4] = {b4.x, b4.y, b4.z, b4.w};
#pragma unroll
            for (int i = 0; i < 4; i++)
#pragma unroll
                for (int j = 0; j < 4; j++) acc[i][j] += av[i] * bv[j];
        }
        __syncthreads();
    }
#pragma unroll
    for (int i = 0; i < 4; i++)
#pragma unroll
        for (int j = 0; j < 4; j++)
            lg[tr * 4 + i][te * 4 + j] = acc[i][j] + bgs[te * 4 + j];
    __syncthreads();

    if (tid < 128) {
        int t = t0 + tid;
        float v1 = -INFINITY; int i1 = 0;
        for (int e = 0; e < 32; e++) { float v = lg[tid][e]; if (v > v1) { v1 = v; i1 = e; } }
        float v2 = -INFINITY; int i2 = 0;
        for (int e = 0; e < 32; e++) {
            if (e == i1) continue;
            float v = lg[tid][e]; if (v > v2) { v2 = v; i2 = e; }
        }
        g_top2[t * 2]     = i1;
        g_top2[t * 2 + 1] = i2;
    }
}

// ---------------- histogram + offsets ----------------
__global__ void hist_kernel() {
    __shared__ int cnt[E_NUM];
    int tid = threadIdx.x;
    if (tid < E_NUM) cnt[tid] = 0;
    __syncthreads();
    for (int f = tid; f < NFLAT; f += 256) atomicAdd(&cnt[g_top2[f]], 1);
    __syncthreads();
    if (tid == 0) {
        int run = 0;
        for (int e = 0; e < E_NUM; e++) { g_offsets[e] = run; run += cnt[e]; }
        g_offsets[E_NUM] = run;
    }
}

// ---------------- stable compaction ----------------
__global__ void compact_kernel() {
    int e = blockIdx.x;
    __shared__ int sc[256];
    __shared__ int base_s;
    int tid = threadIdx.x;
    if (tid == 0) base_s = g_offsets[e];
    __syncthreads();
    for (int s = 0; s < NFLAT; s += 256) {
        int f = s + tid;
        int flag = (g_top2[f] == e) ? 1 : 0;
        sc[tid] = flag;
        __syncthreads();
        for (int o = 1; o < 256; o <<= 1) {
            int v = (tid >= o) ? sc[tid - o] : 0;
            __syncthreads();
            sc[tid] += v;
            __syncthreads();
        }
        if (flag) g_disp[base_s + sc[tid] - 1] = f;
        __syncthreads();
        if (tid == 0) base_s += sc[255];
        __syncthreads();
    }
}

// ---------------- weight transpose + bf16 hi/lo split: [e][k][n] -> [e][n][k] ----------------
__global__ void convert_w_kernel(const float* __restrict__ w1, const float* __restrict__ w2) {
    __shared__ float t[32][33];
    int z = blockIdx.z;
    int widx = z >> 5, e = z & 31;
    const float* W = (widx ? w2 : w1) + (size_t)e * D_DIM * DFF;
    __nv_bfloat16* Oh = g_wh[widx] + (size_t)e * D_DIM * DFF;
    __nv_bfloat16* Ol = g_wl[widx] + (size_t)e * D_DIM * DFF;
    int k0 = blockIdx.x * 32, n0 = blockIdx.y * 32;
    int tx = threadIdx.x & 31, ty = threadIdx.x >> 5;
#pragma unroll
    for (int p = 0; p < 4; ++p) {
        int k = p * 8 + ty;
        t[k][tx] = W[(size_t)(k0 + k) * 1024 + n0 + tx];
    }
    __syncthreads();
#pragma unroll
    for (int p = 0; p < 4; ++p) {
        int n = p * 8 + ty;
        float v = t[tx][n];
        __nv_bfloat16 h = __float2bfloat16(v);
        __nv_bfloat16 l = __float2bfloat16(v - __bfloat162float(h));
        size_t o = (size_t)(n0 + n) * 1024 + k0 + tx;
        Oh[o] = h; Ol[o] = l;
    }
}

// ---------------- gather dispatched rows + bf16 hi/lo split ----------------
__global__ void gather_split_kernel(const float* __restrict__ X) {
    int g = blockIdx.x * 256 + threadIdx.x;   // per float4
    int r = g >> 8, c4 = g & 255;
    int tok = g_disp[r] >> 1;
    float4 v = ((const float4*)X)[(size_t)tok * 256 + c4];
    __nv_bfloat16 hx = __float2bfloat16(v.x), hy = __float2bfloat16(v.y);
    __nv_bfloat16 hz = __float2bfloat16(v.z), hw = __float2bfloat16(v.w);
    __nv_bfloat162* H2 = (__nv_bfloat162*)g_Xh;
    __nv_bfloat162* L2 = (__nv_bfloat162*)g_Xl;
    size_t o = (size_t)r * 512 + c4 * 2;
    H2[o]     = __halves2bfloat162(hx, hy);
    H2[o + 1] = __halves2bfloat162(hz, hw);
    L2[o]     = __halves2bfloat162(__float2bfloat16(v.x - __bfloat162float(hx)),
                                   __float2bfloat16(v.y - __bfloat162float(hy)));
    L2[o + 1] = __halves2bfloat162(__float2bfloat16(v.z - __bfloat162float(hz)),
                                   __float2bfloat16(v.w - __bfloat162float(hw)));
}

// ---------------- warp-MMA grouped GEMM (bf16 hi/lo split, cp.async double buffer) ----------------
// block tile M=128 x N=128, K chunk=32 (NC=32 chunks), 8 warps (2M x 4N), warp tile 64x32.
// smem buffer layout (per buffer, 40960 B): Ah[128][40] | Al | Bh[128][40] | Bl  (80 B row stride)
#define MAT_BYTES 10240
#define BUF_BYTES 40960
#define SMEM_DYN  (2*BUF_BYTES)
#define NC 32

__device__ __forceinline__ void fill_cp(uint32_t sbuf, const char* Ah, const char* Al,
                                        const char* Bh, const char* Bl, int kc, int tid) {
    int kbyte = kc * 64;
#pragma unroll
    for (int half = 0; half < 2; ++half) {
        int idx = tid + half * 256;          // 0..511
        int row = idx >> 2;
        int sg  = (idx & 3) * 16;
        uint32_t dst = sbuf + row * 80 + sg;
        size_t src = (size_t)row * 2048 + kbyte + sg;
        CP16(dst,                 Ah + src);
        CP16(dst + MAT_BYTES,     Al + src);
        CP16(dst + 2 * MAT_BYTES, Bh + src);
        CP16(dst + 3 * MAT_BYTES, Bl + src);
    }
}

__global__ void __launch_bounds__(256)
gemm_mma(int phase, const float* __restrict__ bias1, const float* __restrict__ bias2) {
    int e   = blockIdx.z;
    int off = g_offsets[e];
    int cnt = g_offsets[e + 1] - off;
    int row0 = blockIdx.y * 128;
    if (row0 >= cnt) return;
    int n0 = blockIdx.x * 128;

    extern __shared__ char dsm[];
    uint32_t sb = smem_u32(dsm);

    int tid = threadIdx.x, wid = tid >> 5, lane = tid & 31;
    int g = lane >> 2, tig = lane & 3;
    int m0w = (wid & 1) * 64;        // warp M base in tile
    int n0w = (wid >> 1) * 32;       // warp N base in tile

    const char* Ah = (const char*)((phase ? g_Hh : g_Xh) + (size_t)(off + row0) * 1024);
    const char* Al = (const char*)((phase ? g_Hl : g_Xl) + (size_t)(off + row0) * 1024);
    const char* Bh = (const char*)(g_wh[phase] + ((size_t)e * 1024 + n0) * 1024);
    const char* Bl = (const char*)(g_wl[phase] + ((size_t)e * 1024 + n0) * 1024);
    const float* bias = (phase ? bias2 : bias1) + e * 1024;

    float acc[4][4][4];
#pragma unroll
    for (int mt = 0; mt < 4; mt++)
#pragma unroll
        for (int nt = 0; nt < 4; nt++)
#pragma unroll
            for (int q = 0; q < 4; q++) acc[mt][nt][q] = 0.f;

    fill_cp(sb, Ah, Al, Bh, Bl, 0, tid);
    CP_COMMIT();

    for (int c = 0; c < NC; ++c) {
        if (c + 1 < NC) {
            fill_cp(sb + ((c + 1) & 1) * BUF_BYTES, Ah, Al, Bh, Bl, c + 1, tid);
            CP_COMMIT();
            CP_WAIT(1);
        } else {
            CP_WAIT(0);
        }
        __syncthreads();

        uint32_t abase = sb + (c & 1) * BUF_BYTES;
        uint32_t bbase = abase + 2 * MAT_BYTES;
#pragma unroll
        for (int ks = 0; ks < 2; ++ks) {
            int kb2 = ks * 32 + tig * 4;   // byte offset of (ks*16 + 2*tig) bf16
            uint32_t ah[4][4], al[4][4], bh[4][2], bl[4][2];
#pragma unroll
            for (int mt = 0; mt < 4; mt++) {
                uint32_t r0 = abase + (m0w + mt * 16 + g) * 80 + kb2;
                ah[mt][0] = lds32(r0);       ah[mt][1] = lds32(r0 + 640);
                ah[mt][2] = lds32(r0 + 16);  ah[mt][3] = lds32(r0 + 656);
                uint32_t r1 = r0 + MAT_BYTES;
                al[mt][0] = lds32(r1);       al[mt][1] = lds32(r1 + 640);
                al[mt][2] = lds32(r1 + 16);  al[mt][3] = lds32(r1 + 656);
            }
#pragma unroll
            for (int nt = 0; nt < 4; nt++) {
                uint32_t r0 = bbase + (n0w + nt * 8 + g) * 80 + kb2;
                bh[nt][0] = lds32(r0);  bh[nt][1] = lds32(r0 + 16);
                uint32_t r1 = r0 + MAT_BYTES;
                bl[nt][0] = lds32(r1);  bl[nt][1] = lds32(r1 + 16);
            }
#pragma unroll
            for (int mt = 0; mt < 4; mt++)
#pragma unroll
                for (int nt = 0; nt < 4; nt++) {
                    mma16816(acc[mt][nt], ah[mt], bh[nt]);
                    mma16816(acc[mt][nt], ah[mt], bl[nt]);
                    mma16816(acc[mt][nt], al[mt], bh[nt]);
                }
        }
        __syncthreads();
    }

    // epilogue: +bias, (gelu + bf16 split) or fp32 store
#pragma unroll
    for (int mt = 0; mt < 4; mt++) {
#pragma unroll
        for (int rh = 0; rh < 2; rh++) {
            int m = m0w + mt * 16 + g + rh * 8;
            if (row0 + m >= cnt) continue;
            size_t srow = (size_t)(off + row0 + m);
#pragma unroll
            for (int nt = 0; nt < 4; nt++) {
                int n = n0 + n0w + nt * 8 + 2 * tig;
                float v0 = acc[mt][nt][rh * 2]     + bias[n];
                float v1 = acc[mt][nt][rh * 2 + 1] + bias[n + 1];
                if (phase == 0) {
                    v0 = 0.5f * v0 * (1.0f + erff(v0 * 0.7071067811865475f));
                    v1 = 0.5f * v1 * (1.0f + erff(v1 * 0.7071067811865475f));
                    __nv_bfloat16 h0 = __float2bfloat16(v0);
                    __nv_bfloat16 h1 = __float2bfloat16(v1);
                    *(__nv_bfloat162*)&g_Hh[srow * 1024 + n] = __halves2bfloat162(h0, h1);
                    *(__nv_bfloat162*)&g_Hl[srow * 1024 + n] = __halves2bfloat162(
                        __float2bfloat16(v0 - __bfloat162float(h0)),
                        __float2bfloat16(v1 - __bfloat162float(h1)));
                } else {
                    *(float2*)&g_Y[srow * 1024 + n] = make_float2(v0, v1);
                }
            }
        }
    }
}

// ---------------- pair reduce: out[j] = Y[2j] + Y[2j+1] ----------------
__global__ void reduce_kernel(float* __restrict__ out) {
    int i = blockIdx.x * 256 + threadIdx.x;
    const int n4pr = D_DIM / 4;
    int total = B_TOK * n4pr;
    if (i < total) {
        const float4* Y4 = (const float4*)g_Y;
        float4* O4 = (float4*)out;
        int j  = i / n4pr;
        int n4 = i - j * n4pr;
        float4 a = Y4[(size_t)(2 * j) * n4pr + n4];
        float4 b = Y4[(size_t)(2 * j + 1) * n4pr + n4];
        O4[i] = make_float4(a.x + b.x, a.y + b.y, a.z + b.z, a.w + b.w);
    }
}

__global__ void idx_kernel(float* __restrict__ out) {
    int i = blockIdx.x * 256 + threadIdx.x;
    if (i < NFLAT) out[(size_t)B_TOK * D_DIM + i] = (float)g_top2[i];
}

// ---------------- launch ----------------
extern "C" void kernel_launch(void* const* d_in, const int* in_sizes, int n_in,
                              void* d_out, int out_size) {
    const float* X  = (const float*)d_in[0];
    const float* Wg = (const float*)d_in[1];
    const float* bg = (const float*)d_in[2];
    const float* w1 = (const float*)d_in[3];
    const float* b1 = (const float*)d_in[4];
    const float* w2 = (const float*)d_in[5];
    const float* b2 = (const float*)d_in[6];
    float* out = (float*)d_out;

    cudaFuncSetAttribute(gemm_mma, cudaFuncAttributeMaxDynamicSharedMemorySize, SMEM_DYN);

    convert_w_kernel<<<dim3(32, 32, 64), 256>>>(w1, w2);
    gate_kernel<<<B_TOK / 128, 256>>>(X, Wg, bg);
    hist_kernel<<<1, 256>>>();
    compact_kernel<<<E_NUM, 256>>>();
    gather_split_kernel<<<NFLAT, 256>>>(X);

    dim3 ggrid(DFF / 128, NFLAT / 128, E_NUM);   // (8, 128, 32); empty tiles early-exit
    gemm_mma<<<ggrid, 256, SMEM_DYN>>>(0, b1, b2);
    gemm_mma<<<ggrid, 256, SMEM_DYN>>>(1, b1, b2);

    reduce_kernel<<<(B_TOK * (D_DIM / 4) + 255) / 256, 256>>>(out);
    if (out_size >= B_TOK * D_DIM + NFLAT)
        idx_kernel<<<(NFLAT + 255) / 256, 256>>>(out);
}